// round 9
// baseline (speedup 1.0000x reference)
#include <cuda_runtime.h>
#include <cstdint>

// Problem constants
#define Bc 64
#define Cc 256
#define Hc 28
#define Wc 28
#define Nc 784            // H*W
#define CH 32             // channel chunk
#define NCHUNK (Cc / CH)  // 8
#define BROWS 4           // fixed band rows
#define BN (BROWS * Wc)   // 112 (constant band width)
#define NQZ (BN / 4)      // 28 16B-groups per z row
#define MAXK 16           // max pairs per (view,column); provable <= ~9
#define NG (2 * Wc)       // 56 groups: view*28 + column
#define ZOFF1 (CH * BN + 4)

#define NZOP 7            // z cp.asyncs per thread: 2*CH*NQZ/256 = 1792/256
#define NYOPMAX 2         // y cp.asyncs per thread: 448 total -> t<192 has 2

__device__ double g_sum[2];
__device__ unsigned long long g_cnt[2];

__global__ void cl_init_kernel() {
    g_sum[0] = 0.0; g_sum[1] = 0.0;
    g_cnt[0] = 0ull; g_cnt[1] = 0ull;
}

__device__ __forceinline__ void cp_async16(unsigned int smem_addr, const void* gptr) {
    asm volatile("cp.async.cg.shared.global [%0], [%1], 16;\n" :: "r"(smem_addr), "l"(gptr));
}
__device__ __forceinline__ void cp_async_commit_wait() {
    asm volatile("cp.async.commit_group;\n" ::: "memory");
    asm volatile("cp.async.wait_group 0;\n" ::: "memory");
}

__global__ __launch_bounds__(256) void cl_main_kernel(
    const float* __restrict__ y1, const float* __restrict__ y2,
    const float* __restrict__ z1, const float* __restrict__ z2,
    const float* __restrict__ g1, const float* __restrict__ g2)
{
    __shared__ float ysm[2 * CH * Wc];       // [view][c][nl]
    __shared__ float zsm[2 * CH * BN + 4];   // [view][c][j], view1 at +ZOFF1
    __shared__ float yn2[2][Wc];
    __shared__ float zn2[2][BN];
    __shared__ float s_g1x[Wc];
    __shared__ float s_g2y[BN];
    __shared__ float s_g2x[BN];
    __shared__ int   s_cnt[NG];
    __shared__ int   s_jl[NG * MAXK];
    __shared__ float s_dot[NG * MAXK];
    __shared__ int   s_r0;
    __shared__ float s_bin1, s_bin2, s_g1y;
    __shared__ double s_acc[2];
    __shared__ unsigned int s_pc[2];

    const int yr = blockIdx.x;  // grid1 row 0..27
    const int b  = blockIdx.y;  // batch
    const int t  = threadIdx.x;

    const float* g1b = g1 + (size_t)b * 2 * Nc;
    const float* g2b = g2 + (size_t)b * 2 * Nc;

    if (t == 0) {
        float d1y = g1b[29] - g1b[0];
        float d1x = g1b[Nc + 29] - g1b[Nc + 0];
        float bin1 = __fsqrt_rn(__fadd_rn(__fmul_rn(d1y, d1y), __fmul_rn(d1x, d1x)));
        float d2y = g2b[29] - g2b[0];
        float d2x = g2b[Nc + 29] - g2b[Nc + 0];
        float bin2 = __fsqrt_rn(__fadd_rn(__fmul_rn(d2y, d2y), __fmul_rn(d2x, d2x)));
        s_bin1 = bin1; s_bin2 = bin2;
        float g1y = g1b[yr * Wc];
        s_g1y = g1y;
        float thrm = 0.7f * fmaxf(bin1, bin2) * 1.0002f + 1e-3f;
        int r0 = -1;
        for (int my = 0; my < Hc; my++) {
            float gy = g2b[my * Wc];
            if (fabsf(gy - g1y) <= thrm) { if (r0 < 0) r0 = my; }
        }
        // clamp to fixed 4-row window (always superset of true band)
        if (r0 < 0) r0 = -1;
        else if (r0 > Hc - BROWS) r0 = Hc - BROWS;
        s_r0 = r0;
        s_acc[0] = 0.0; s_acc[1] = 0.0;
        s_pc[0] = 0u; s_pc[1] = 0u;
    }
    __syncthreads();

    const int r0 = s_r0;
    if (r0 < 0) return;                 // uniform exit
    const int m0 = r0 * Wc;
    const int nbase = yr * Wc;

    // stage grid coords, zero accumulators and group tables (all constant bounds)
    if (t < Wc) s_g1x[t] = g1b[Nc + nbase + t];
    if (t < BN) { s_g2y[t] = g2b[m0 + t]; s_g2x[t] = g2b[Nc + m0 + t]; }
    if (t < 2 * Wc) yn2[t / Wc][t % Wc] = 0.f;
    if (t < 2 * BN - 32) { int u = t + 32; }   // (no-op placeholder removed below)
    for (int j = t; j < 2 * BN; j += 256) zn2[j / BN][j % BN] = 0.f;
    if (t < NG) s_cnt[t] = 0;
    for (int k = t; k < NG * MAXK; k += 256) s_dot[k] = 0.f;
    __syncthreads();

    // ---- exact mask evaluation (bit-matches reference float ops) ----
    const float bin1 = s_bin1, bin2 = s_bin2, g1y = s_g1y;
    #pragma unroll 1
    for (int idx = t; idx < Wc * BN; idx += 256) {
        int nl = idx / BN;              // constant divisor
        int j  = idx - nl * BN;
        float dy = g1y - s_g2y[j];
        float dx = s_g1x[nl] - s_g2x[j];
        float dist = __fsqrt_rn(__fadd_rn(__fmul_rn(dy, dy), __fmul_rn(dx, dx)));
        bool m1 = (__fdiv_rn(dist, bin1) <= 0.7f);
        bool m2 = (__fdiv_rn(dist, bin2) <= 0.7f);
        if (m1) { int k = atomicAdd(&s_cnt[nl], 1);      if (k < MAXK) s_jl[nl * MAXK + k] = j; }
        if (m2) { int k = atomicAdd(&s_cnt[Wc + nl], 1); if (k < MAXK) s_jl[(Wc + nl) * MAXK + k] = j; }
    }
    __syncthreads();

    // view 0: y1 vs z2 ; view 1: y2 vs z1
    const float* ya0 = y1 + (size_t)b * Cc * Nc;
    const float* ya1 = y2 + (size_t)b * Cc * Nc;
    const float* za0 = z2 + (size_t)b * Cc * Nc;
    const float* za1 = z1 + (size_t)b * Cc * Nc;

    unsigned int ysm0 = (unsigned int)__cvta_generic_to_shared(ysm);
    unsigned int zsm0 = (unsigned int)__cvta_generic_to_shared(zsm);

    // ---- precompute all cp.async address pairs (hoisted out of chunk loop) ----
    const float* zg[NZOP];
    unsigned int  zs[NZOP];
    #pragma unroll
    for (int i = 0; i < NZOP; i++) {
        int e  = t + 256 * i;           // 0..1791
        int v  = e / (CH * NQZ);        // constant divisors
        int r  = e - v * (CH * NQZ);
        int cl = r / NQZ;
        int q  = r - cl * NQZ;
        zs[i] = zsm0 + (unsigned int)((v * ZOFF1 + cl * BN + (q << 2)) * 4);
        zg[i] = (v ? za1 : za0) + (size_t)cl * Nc + m0 + (q << 2);
    }
    const float* ygp[NYOPMAX];
    unsigned int  ys[NYOPMAX];
    int nyop = (t < 192) ? 2 : 1;       // 448 total ops
    #pragma unroll
    for (int i = 0; i < NYOPMAX; i++) {
        int e  = t + 256 * i;
        if (e < 2 * CH * (Wc / 4)) {
            int v  = e / (CH * (Wc / 4));
            int r  = e - v * (CH * (Wc / 4));
            int cl = r / (Wc / 4);
            int q  = r - cl * (Wc / 4);
            ys[i]  = ysm0 + (unsigned int)(((v * CH + cl) * Wc + (q << 2)) * 4);
            ygp[i] = (v ? ya1 : ya0) + (size_t)cl * Nc + nbase + (q << 2);
        } else { ys[i] = ysm0; ygp[i] = ya0; }
    }

    // dot-phase thread mapping: warp0 -> view0 cols, warp1 -> view1 cols
    const int dv  = t >> 5;
    const int dnl = t & 31;
    const bool dotthr = (t < 64) && (dnl < Wc);
    int dg = 0, dcnt = 0;
    if (dotthr) { dg = dv * Wc + dnl; dcnt = s_cnt[dg]; if (dcnt > MAXK) dcnt = MAXK; }

    // ---- chunk loop (minimal per-chunk addressing) ----
    #pragma unroll 1
    for (int ci = 0; ci < NCHUNK; ci++) {
        __syncthreads();   // previous chunk's readers done before refill
        #pragma unroll
        for (int i = 0; i < NZOP; i++) {
            cp_async16(zs[i], zg[i]);
            zg[i] += CH * Nc;
        }
        cp_async16(ys[0], ygp[0]); ygp[0] += CH * Nc;
        if (nyop == 2) { cp_async16(ys[1], ygp[1]); ygp[1] += CH * Nc; }
        cp_async_commit_wait();
        __syncthreads();

        // column norms^2 (constant bounds; lanes take consecutive cols)
        if (t < 2 * Wc) {
            int v = t / Wc, nl = t - v * Wc;
            const float* yv = ysm + v * CH * Wc;
            float s = 0.f;
            #pragma unroll
            for (int cl = 0; cl < CH; cl++) { float x = yv[cl * Wc + nl]; s += x * x; }
            yn2[v][nl] += s;
        }
        if (t < 2 * BN) {
            int v = t / BN, j = t - v * BN;
            const float* zv = zsm + v * ZOFF1;
            float s = 0.f;
            #pragma unroll
            for (int cl = 0; cl < CH; cl++) { float x = zv[cl * BN + j]; s += x * x; }
            zn2[v][j] += s;
        }

        // column-owned pair dots: y column cached in registers
        if (dotthr && dcnt > 0) {
            const float* yv = ysm + dv * CH * Wc;
            const float* zv = zsm + dv * ZOFF1;
            float yreg[CH];
            #pragma unroll
            for (int cl = 0; cl < CH; cl++) yreg[cl] = yv[cl * Wc + dnl];
            #pragma unroll 1
            for (int k = 0; k < dcnt; k++) {
                int j = s_jl[dg * MAXK + k];
                float s = 0.f;
                #pragma unroll
                for (int cl = 0; cl < CH; cl++) s += yreg[cl] * zv[cl * BN + j];
                s_dot[dg * MAXK + k] += s;
            }
        }
    }
    __syncthreads();

    // ---- per-pair cosine sims, double accumulation ----
    if (dotthr && dcnt > 0) {
        double ls = 0.0;
        for (int k = 0; k < dcnt; k++) {
            int j = s_jl[dg * MAXK + k];
            float den = fmaxf(__fsqrt_rn(yn2[dv][dnl] * zn2[dv][j]), 1e-8f);
            ls += (double)(s_dot[dg * MAXK + k] / den);
        }
        atomicAdd(&s_acc[dv], ls);
        atomicAdd(&s_pc[dv], (unsigned int)dcnt);
    }
    __syncthreads();
    if (t == 0) {
        atomicAdd(&g_sum[0], s_acc[0]);
        atomicAdd(&g_sum[1], s_acc[1]);
        atomicAdd(&g_cnt[0], (unsigned long long)s_pc[0]);
        atomicAdd(&g_cnt[1], (unsigned long long)s_pc[1]);
    }
}

__global__ void cl_fin_kernel(float* __restrict__ out) {
    double l0 = g_cnt[0] ? g_sum[0] / (double)g_cnt[0] : 0.0;
    double l1 = g_cnt[1] ? g_sum[1] / (double)g_cnt[1] : 0.0;
    out[0] = (float)(-(l0 + l1));
}

extern "C" void kernel_launch(void* const* d_in, const int* in_sizes, int n_in,
                              void* d_out, int out_size) {
    (void)in_sizes; (void)n_in; (void)out_size;
    const float* y1 = (const float*)d_in[0];
    const float* y2 = (const float*)d_in[1];
    const float* z1 = (const float*)d_in[2];
    const float* z2 = (const float*)d_in[3];
    const float* g1 = (const float*)d_in[4];
    const float* g2 = (const float*)d_in[5];

    cl_init_kernel<<<1, 1>>>();
    dim3 grid(Hc, Bc);
    cl_main_kernel<<<grid, 256>>>(y1, y2, z1, z2, g1, g2);
    cl_fin_kernel<<<1, 1>>>((float*)d_out);
}

// round 11
// speedup vs baseline: 1.4224x; 1.4224x over previous
#include <cuda_runtime.h>
#include <cstdint>

// Problem constants
#define Bc 64
#define Cc 256
#define Hc 28
#define Wc 28
#define Nc 784            // H*W
#define ROWS 2            // y rows per block
#define NBX (Hc / ROWS)   // 14
#define NBLK (NBX * Bc)   // 896
#define YC (ROWS * Wc)    // 56 y columns per view
#define BROWS 5           // fixed z band rows (provable superset)
#define BN (BROWS * Wc)   // 140
#define NQZ (BN / 4)      // 35
#define NQY (YC / 4)      // 14
#define CH 16             // channel chunk
#define NCHUNK (Cc / CH)  // 16
#define NG (2 * YC)       // 112 groups: view*56 + ycol
#define MAXK 8            // max pairs per group (provable <= 6)
#define ZOFF1 (CH * BN + 4)

__device__ double g_part[2 * NBLK];
__device__ int    g_pcnt[2 * NBLK];

__device__ __forceinline__ void cp_async16(unsigned int smem_addr, const void* gptr) {
    asm volatile("cp.async.cg.shared.global [%0], [%1], 16;\n" :: "r"(smem_addr), "l"(gptr));
}
__device__ __forceinline__ void cp_async_commit() {
    asm volatile("cp.async.commit_group;\n" ::: "memory");
}
__device__ __forceinline__ void cp_async_wait0() {
    asm volatile("cp.async.wait_group 0;\n" ::: "memory");
}

__global__ __launch_bounds__(256) void cl_main_kernel(
    const float* __restrict__ y1, const float* __restrict__ y2,
    const float* __restrict__ z1, const float* __restrict__ z2,
    const float* __restrict__ g1, const float* __restrict__ g2)
{
    __shared__ float ysm[2 * CH * YC];       // [view][c][ycol]
    __shared__ float zsm[2 * CH * BN + 4];   // [view][c][j], view1 at +ZOFF1
    __shared__ float yn2[2 * YC];
    __shared__ float zn2[2 * BN];
    __shared__ float s_g1yc[YC];             // y coord per y column
    __shared__ float s_g1x[YC];
    __shared__ float s_g2y[BN];
    __shared__ float s_g2x[BN];
    __shared__ int   s_cnt[NG];
    __shared__ int   s_jl[NG * MAXK];
    __shared__ int   s_r0;
    __shared__ float s_bin1, s_bin2, s_g1ya, s_g1yb;
    __shared__ double warp_s0[8], warp_s1[8];
    __shared__ int    warp_c0[8], warp_c1[8];

    const int bx = blockIdx.x;   // y row-pair 0..13
    const int b  = blockIdx.y;   // batch
    const int t  = threadIdx.x;
    const int blk = b * NBX + bx;
    const int nbase = bx * YC;   // global y col base (rows 2bx,2bx+1 contiguous)

    const float* g1b = g1 + (size_t)b * 2 * Nc;
    const float* g2b = g2 + (size_t)b * 2 * Nc;

    if (t == 0) {
        float d1y = g1b[29] - g1b[0];
        float d1x = g1b[Nc + 29] - g1b[Nc + 0];
        float bin1 = __fsqrt_rn(__fadd_rn(__fmul_rn(d1y, d1y), __fmul_rn(d1x, d1x)));
        float d2y = g2b[29] - g2b[0];
        float d2x = g2b[Nc + 29] - g2b[Nc + 0];
        float bin2 = __fsqrt_rn(__fadd_rn(__fmul_rn(d2y, d2y), __fmul_rn(d2x, d2x)));
        s_bin1 = bin1; s_bin2 = bin2;
        float g1ya = g1b[(2 * bx) * Wc];       // row 2bx y coord
        float g1yb = g1b[(2 * bx + 1) * Wc];   // row 2bx+1 y coord
        s_g1ya = g1ya; s_g1yb = g1yb;
        float thrm = 0.7f * fmaxf(bin1, bin2) * 1.0002f + 1e-3f;
        int r0 = -1;
        for (int my = 0; my < Hc; my++) {
            float gy = g2b[my * Wc];
            if (gy >= g1ya - thrm && gy <= g1yb + thrm) { r0 = my; break; }
        }
        if (r0 > Hc - BROWS) r0 = Hc - BROWS;
        s_r0 = r0;
    }
    __syncthreads();

    const int r0 = s_r0;
    if (r0 < 0) {                // uniform exit: still write deterministic zeros
        if (t == 0) {
            g_part[blk] = 0.0; g_part[NBLK + blk] = 0.0;
            g_pcnt[blk] = 0;    g_pcnt[NBLK + blk] = 0;
        }
        return;
    }
    const int m0 = r0 * Wc;

    // view 0: y1 vs z2 ; view 1: y2 vs z1
    const float* yb0 = y1 + (size_t)b * Cc * Nc;
    const float* yb1 = y2 + (size_t)b * Cc * Nc;
    const float* zb0 = z2 + (size_t)b * Cc * Nc;
    const float* zb1 = z1 + (size_t)b * Cc * Nc;

    unsigned int ysm0 = (unsigned int)__cvta_generic_to_shared(ysm);
    unsigned int zsm0 = (unsigned int)__cvta_generic_to_shared(zsm);

    // ---- prologue: issue chunk-0 loads (overlap DRAM with mask eval) ----
    {
        #pragma unroll
        for (int i = 0; i < 5; i++) {          // z: 2*CH*NQZ = 1120 ops
            int e = t + 256 * i;
            if (e < 2 * CH * NQZ) {
                int v  = e / (CH * NQZ);
                int r  = e - v * (CH * NQZ);
                int cl = r / NQZ;
                int q  = r - cl * NQZ;
                cp_async16(zsm0 + (unsigned int)((v * ZOFF1 + cl * BN + (q << 2)) * 4),
                           (v ? zb1 : zb0) + (size_t)cl * Nc + m0 + (q << 2));
            }
        }
        #pragma unroll
        for (int i = 0; i < 2; i++) {          // y: 2*CH*NQY = 448 ops
            int e = t + 256 * i;
            if (e < 2 * CH * NQY) {
                int v  = e / (CH * NQY);
                int r  = e - v * (CH * NQY);
                int cl = r / NQY;
                int q  = r - cl * NQY;
                cp_async16(ysm0 + (unsigned int)(((v * CH + cl) * YC + (q << 2)) * 4),
                           (v ? yb1 : yb0) + (size_t)cl * Nc + nbase + (q << 2));
            }
        }
        cp_async_commit();
    }

    // stage grid coords, zero norms & counts
    if (t < YC) {
        s_g1x[t]  = g1b[Nc + nbase + t];
        s_g1yc[t] = (t < Wc) ? s_g1ya : s_g1yb;
        yn2[t] = 0.f; yn2[YC + t] = 0.f;
    }
    if (t < BN) {
        s_g2y[t] = g2b[m0 + t];
        s_g2x[t] = g2b[Nc + m0 + t];
        zn2[t] = 0.f; zn2[BN + t] = 0.f;
    }
    if (t < NG) s_cnt[t] = 0;
    __syncthreads();

    // ---- exact mask evaluation (bit-matches reference float ops) ----
    const float bin1 = s_bin1, bin2 = s_bin2;
    #pragma unroll 1
    for (int idx = t; idx < YC * BN; idx += 256) {   // 7840 evals
        int nl = idx / BN;                // constant divisor
        int j  = idx - nl * BN;
        float dy = s_g1yc[nl] - s_g2y[j];
        float dx = s_g1x[nl] - s_g2x[j];
        float dist = __fsqrt_rn(__fadd_rn(__fmul_rn(dy, dy), __fmul_rn(dx, dx)));
        bool m1 = (__fdiv_rn(dist, bin1) <= 0.7f);
        bool m2 = (__fdiv_rn(dist, bin2) <= 0.7f);
        if (m1) { int k = atomicAdd(&s_cnt[nl], 1);      if (k < MAXK) s_jl[nl * MAXK + k] = j; }
        if (m2) { int k = atomicAdd(&s_cnt[YC + nl], 1); if (k < MAXK) s_jl[(YC + nl) * MAXK + k] = j; }
    }
    __syncthreads();

    // dot-phase mapping: thread t<112 owns group t; register-resident pair state
    const int dv  = (t < NG) ? (t / YC) : 0;
    const int dyc = (t < NG) ? (t - dv * YC) : 0;
    int dcnt = 0;
    int   jreg[MAXK];
    float dreg[MAXK];
    #pragma unroll
    for (int k = 0; k < MAXK; k++) { jreg[k] = 0; dreg[k] = 0.f; }
    if (t < NG) {
        dcnt = s_cnt[t]; if (dcnt > MAXK) dcnt = MAXK;
        #pragma unroll
        for (int k = 0; k < MAXK; k++) if (k < dcnt) jreg[k] = s_jl[t * MAXK + k];
    }

    // ---- chunk loop (single buffer, R6-proven structure) ----
    #pragma unroll 1
    for (int ci = 0; ci < NCHUNK; ci++) {
        cp_async_wait0();
        __syncthreads();

        // y column norms^2: 112 cols, conflict-free
        if (t < 2 * YC) {
            int v = t / YC, yc = t - v * YC;
            const float* yv = ysm + v * CH * YC;
            float s = 0.f;
            #pragma unroll
            for (int cl = 0; cl < CH; cl++) { float x = yv[cl * YC + yc]; s += x * x; }
            yn2[t] += s;
        }
        // z column norms^2: 280 cols
        #pragma unroll
        for (int i = 0; i < 2; i++) {
            int idx = t + 256 * i;
            if (idx < 2 * BN) {
                int v = idx / BN, j = idx - v * BN;
                const float* zv = zsm + v * ZOFF1;
                float s = 0.f;
                #pragma unroll
                for (int cl = 0; cl < CH; cl++) { float x = zv[cl * BN + j]; s += x * x; }
                zn2[idx] += s;
            }
        }
        // column-owned pair dots: y column cached in registers, dots in registers
        if (t < NG && dcnt > 0) {
            const float* yv = ysm + dv * CH * YC;
            const float* zv = zsm + dv * ZOFF1;
            float yreg[CH];
            #pragma unroll
            for (int cl = 0; cl < CH; cl++) yreg[cl] = yv[cl * YC + dyc];
            #pragma unroll
            for (int k = 0; k < MAXK; k++) {
                if (k < dcnt) {
                    int j = jreg[k];
                    float s = 0.f;
                    #pragma unroll
                    for (int cl = 0; cl < CH; cl++) s += yreg[cl] * zv[cl * BN + j];
                    dreg[k] += s;
                }
            }
        }
        __syncthreads();

        // issue next chunk's loads (buffer free now)
        if (ci + 1 < NCHUNK) {
            const int cc = (ci + 1) * CH;
            #pragma unroll
            for (int i = 0; i < 5; i++) {
                int e = t + 256 * i;
                if (e < 2 * CH * NQZ) {
                    int v  = e / (CH * NQZ);
                    int r  = e - v * (CH * NQZ);
                    int cl = r / NQZ;
                    int q  = r - cl * NQZ;
                    cp_async16(zsm0 + (unsigned int)((v * ZOFF1 + cl * BN + (q << 2)) * 4),
                               (v ? zb1 : zb0) + (size_t)(cc + cl) * Nc + m0 + (q << 2));
                }
            }
            #pragma unroll
            for (int i = 0; i < 2; i++) {
                int e = t + 256 * i;
                if (e < 2 * CH * NQY) {
                    int v  = e / (CH * NQY);
                    int r  = e - v * (CH * NQY);
                    int cl = r / NQY;
                    int q  = r - cl * NQY;
                    cp_async16(ysm0 + (unsigned int)(((v * CH + cl) * YC + (q << 2)) * 4),
                               (v ? yb1 : yb0) + (size_t)(cc + cl) * Nc + nbase + (q << 2));
                }
            }
            cp_async_commit();
        }
    }

    // ---- per-pair cosine sims, per-view block reduction ----
    double ls0 = 0.0, ls1 = 0.0;
    int lc0 = 0, lc1 = 0;
    if (t < NG && dcnt > 0) {
        float myn = yn2[t];
        double ls = 0.0;
        #pragma unroll
        for (int k = 0; k < MAXK; k++) {
            if (k < dcnt) {
                int j = jreg[k];
                float den = fmaxf(__fsqrt_rn(myn * zn2[dv * BN + j]), 1e-8f);
                ls += (double)(dreg[k] / den);
            }
        }
        if (dv == 0) { ls0 = ls; lc0 = dcnt; }
        else         { ls1 = ls; lc1 = dcnt; }
    }
    for (int off = 16; off; off >>= 1) {
        ls0 += __shfl_down_sync(0xffffffffu, ls0, off);
        ls1 += __shfl_down_sync(0xffffffffu, ls1, off);
        lc0 += __shfl_down_sync(0xffffffffu, lc0, off);
        lc1 += __shfl_down_sync(0xffffffffu, lc1, off);
    }
    int wid = t >> 5, lane = t & 31;
    if (lane == 0) { warp_s0[wid] = ls0; warp_s1[wid] = ls1; warp_c0[wid] = lc0; warp_c1[wid] = lc1; }
    __syncthreads();
    if (t == 0) {
        double S0 = 0.0, S1 = 0.0; int C0 = 0, C1 = 0;
        #pragma unroll
        for (int w = 0; w < 8; w++) { S0 += warp_s0[w]; S1 += warp_s1[w]; C0 += warp_c0[w]; C1 += warp_c1[w]; }
        g_part[blk] = S0; g_part[NBLK + blk] = S1;
        g_pcnt[blk] = C0; g_pcnt[NBLK + blk] = C1;
    }
}

__global__ __launch_bounds__(256) void cl_fin_kernel(float* __restrict__ out) {
    __shared__ double rs0[8], rs1[8];
    __shared__ double rc0[8], rc1[8];
    int t = threadIdx.x;
    double s0 = 0.0, s1 = 0.0, c0 = 0.0, c1 = 0.0;
    for (int i = t; i < NBLK; i += 256) {
        s0 += g_part[i]; s1 += g_part[NBLK + i];
        c0 += (double)g_pcnt[i]; c1 += (double)g_pcnt[NBLK + i];
    }
    for (int off = 16; off; off >>= 1) {
        s0 += __shfl_down_sync(0xffffffffu, s0, off);
        s1 += __shfl_down_sync(0xffffffffu, s1, off);
        c0 += __shfl_down_sync(0xffffffffu, c0, off);
        c1 += __shfl_down_sync(0xffffffffu, c1, off);
    }
    int wid = t >> 5, lane = t & 31;
    if (lane == 0) { rs0[wid] = s0; rs1[wid] = s1; rc0[wid] = c0; rc1[wid] = c1; }
    __syncthreads();
    if (t == 0) {
        double S0 = 0, S1 = 0, C0 = 0, C1 = 0;
        #pragma unroll
        for (int w = 0; w < 8; w++) { S0 += rs0[w]; S1 += rs1[w]; C0 += rc0[w]; C1 += rc1[w]; }
        double l0 = (C0 > 0.0) ? S0 / C0 : 0.0;
        double l1 = (C1 > 0.0) ? S1 / C1 : 0.0;
        out[0] = (float)(-(l0 + l1));
    }
}

extern "C" void kernel_launch(void* const* d_in, const int* in_sizes, int n_in,
                              void* d_out, int out_size) {
    (void)in_sizes; (void)n_in; (void)out_size;
    const float* y1 = (const float*)d_in[0];
    const float* y2 = (const float*)d_in[1];
    const float* z1 = (const float*)d_in[2];
    const float* z2 = (const float*)d_in[3];
    const float* g1 = (const float*)d_in[4];
    const float* g2 = (const float*)d_in[5];

    dim3 grid(NBX, Bc);
    cl_main_kernel<<<grid, 256>>>(y1, y2, z1, z2, g1, g2);
    cl_fin_kernel<<<1, 256>>>((float*)d_out);
}

// round 12
// speedup vs baseline: 1.4828x; 1.0424x over previous
#include <cuda_runtime.h>
#include <cstdint>

// Problem constants
#define Bc 64
#define Cc 256
#define Hc 28
#define Wc 28
#define Nc 784            // H*W
#define CH 32             // channel chunk
#define NCHUNK (Cc / CH)  // 8
#define BROWS 4           // max grid2 band rows (provable <= 4)
#define BN (BROWS * Wc)   // 112
#define MAXK 16           // max pairs per (view,column); provable <= ~9
#define NG (2 * Wc)       // 56 groups: view*28 + column
#define ZOFF1 (CH * BN + 4)
#define NBLK (Hc * Bc)    // 1792 blocks

__device__ double g_part[2 * NBLK];
__device__ int    g_pcnt[2 * NBLK];
__device__ unsigned int g_done = 0;

__device__ __forceinline__ void cp_async16(unsigned int smem_addr, const void* gptr) {
    asm volatile("cp.async.cg.shared.global [%0], [%1], 16;\n" :: "r"(smem_addr), "l"(gptr));
}
__device__ __forceinline__ void cp_async_commit_wait() {
    asm volatile("cp.async.commit_group;\n" ::: "memory");
    asm volatile("cp.async.wait_group 0;\n" ::: "memory");
}

__global__ __launch_bounds__(256) void cl_main_kernel(
    const float* __restrict__ y1, const float* __restrict__ y2,
    const float* __restrict__ z1, const float* __restrict__ z2,
    const float* __restrict__ g1, const float* __restrict__ g2,
    float* __restrict__ out)
{
    __shared__ float ysm[2 * CH * Wc];       // [view][c][nl]
    __shared__ float zsm[2 * CH * BN + 4];   // [view][c][j], view1 at +ZOFF1
    __shared__ float yn2[2][Wc];
    __shared__ float zn2[2][BN];
    __shared__ float s_g1x[Wc];
    __shared__ float s_g2y[BN];
    __shared__ float s_g2x[BN];
    __shared__ int   s_cnt[NG];
    __shared__ int   s_jl[NG * MAXK];
    __shared__ float s_dot[NG * MAXK];
    __shared__ int   s_r0, s_nb;
    __shared__ float s_bin1, s_bin2, s_g1y;
    __shared__ double s_acc[2];
    __shared__ unsigned int s_pc[2];
    __shared__ int s_last;
    __shared__ double red_s0[8], red_s1[8], red_c0[8], red_c1[8];

    const int yr = blockIdx.x;  // grid1 row 0..27
    const int b  = blockIdx.y;  // batch
    const int t  = threadIdx.x;
    const int blk = b * Hc + yr;

    const float* g1b = g1 + (size_t)b * 2 * Nc;
    const float* g2b = g2 + (size_t)b * 2 * Nc;

    if (t == 0) {
        float d1y = g1b[29] - g1b[0];
        float d1x = g1b[Nc + 29] - g1b[Nc + 0];
        float bin1 = __fsqrt_rn(__fadd_rn(__fmul_rn(d1y, d1y), __fmul_rn(d1x, d1x)));
        float d2y = g2b[29] - g2b[0];
        float d2x = g2b[Nc + 29] - g2b[Nc + 0];
        float bin2 = __fsqrt_rn(__fadd_rn(__fmul_rn(d2y, d2y), __fmul_rn(d2x, d2x)));
        s_bin1 = bin1; s_bin2 = bin2;
        float g1y = g1b[yr * Wc];
        s_g1y = g1y;
        float thrm = 0.7f * fmaxf(bin1, bin2) * 1.0002f + 1e-3f;
        int r0 = -1, r1 = -2;
        for (int my = 0; my < Hc; my++) {
            float gy = g2b[my * Wc];
            if (fabsf(gy - g1y) <= thrm) { if (r0 < 0) r0 = my; r1 = my; }
        }
        int nb = r1 - r0 + 1;
        if (nb < 0) nb = 0;
        if (nb > BROWS) nb = BROWS;
        s_r0 = r0; s_nb = nb;
        s_acc[0] = 0.0; s_acc[1] = 0.0;
        s_pc[0] = 0u; s_pc[1] = 0u;
    }
    __syncthreads();

    const int nb = s_nb;
    if (nb > 0) {                       // ---- active path ----
        const int r0 = s_r0;
        const int m0 = r0 * Wc;
        const int bandn = nb * Wc;      // <= 112, multiple of 28
        const int nqz = bandn >> 2;
        const int nbase = yr * Wc;

        // stage grid coords, zero accumulators and group tables
        if (t < Wc) s_g1x[t] = g1b[Nc + nbase + t];
        for (int j = t; j < bandn; j += 256) {
            s_g2y[j] = g2b[m0 + j];
            s_g2x[j] = g2b[Nc + m0 + j];
        }
        if (t < 2 * Wc) yn2[t / Wc][t % Wc] = 0.f;
        for (int j = t; j < 2 * BN; j += 256) zn2[j / BN][j % BN] = 0.f;
        if (t < NG) s_cnt[t] = 0;
        for (int k = t; k < NG * MAXK; k += 256) s_dot[k] = 0.f;
        __syncthreads();

        // ---- exact mask evaluation (bit-matches reference float ops) ----
        const float bin1 = s_bin1, bin2 = s_bin2, g1y = s_g1y;
        for (int idx = t; idx < Wc * bandn; idx += 256) {
            int nl = idx / bandn;
            int j  = idx - nl * bandn;
            float dy = g1y - s_g2y[j];
            float dx = s_g1x[nl] - s_g2x[j];
            float dist = __fsqrt_rn(__fadd_rn(__fmul_rn(dy, dy), __fmul_rn(dx, dx)));
            bool m1 = (__fdiv_rn(dist, bin1) <= 0.7f);
            bool m2 = (__fdiv_rn(dist, bin2) <= 0.7f);
            if (m1) { int k = atomicAdd(&s_cnt[nl], 1);      if (k < MAXK) s_jl[nl * MAXK + k] = j; }
            if (m2) { int k = atomicAdd(&s_cnt[Wc + nl], 1); if (k < MAXK) s_jl[(Wc + nl) * MAXK + k] = j; }
        }
        __syncthreads();

        // view 0: y1 vs z2 ; view 1: y2 vs z1
        const float* ya[2] = { y1 + (size_t)b * Cc * Nc, y2 + (size_t)b * Cc * Nc };
        const float* za[2] = { z2 + (size_t)b * Cc * Nc, z1 + (size_t)b * Cc * Nc };

        unsigned int ysm0 = (unsigned int)__cvta_generic_to_shared(ysm);
        unsigned int zsm0 = (unsigned int)__cvta_generic_to_shared(zsm);

        // dot-phase thread mapping: warp0 -> view0 cols, warp1 -> view1 cols
        const int dv  = t >> 5;
        const int dnl = t & 31;
        const bool dotthr = (t < 64) && (dnl < Wc);
        int dg = 0, dcnt = 0;
        if (dotthr) { dg = dv * Wc + dnl; dcnt = s_cnt[dg]; if (dcnt > MAXK) dcnt = MAXK; }

        // ---- chunk loop ----
        for (int ci = 0; ci < NCHUNK; ci++) {
            const int cc = ci * CH;
            __syncthreads();   // previous chunk's readers done before refill
            for (int e = t; e < 2 * CH * (Wc / 4); e += 256) {
                int v  = e / (CH * (Wc / 4));
                int r  = e - v * (CH * (Wc / 4));
                int cl = r / (Wc / 4);
                int q  = r - cl * (Wc / 4);
                unsigned int saddr = ysm0 + (unsigned int)(((v * CH + cl) * Wc + (q << 2)) * 4);
                cp_async16(saddr, ya[v] + (size_t)(cc + cl) * Nc + nbase + (q << 2));
            }
            for (int e = t; e < 2 * CH * nqz; e += 256) {
                int v  = e / (CH * nqz);
                int r  = e - v * (CH * nqz);
                int cl = r / nqz;
                int q  = r - cl * nqz;
                unsigned int saddr = zsm0 + (unsigned int)((v * ZOFF1 + cl * BN + (q << 2)) * 4);
                cp_async16(saddr, za[v] + (size_t)(cc + cl) * Nc + m0 + (q << 2));
            }
            cp_async_commit_wait();
            __syncthreads();

            // column norms^2 (lanes: consecutive cols -> conflict-free)
            for (int col = t; col < 2 * Wc; col += 256) {
                int v = col / Wc, nl = col - v * Wc;
                const float* yv = ysm + v * CH * Wc;
                float s = 0.f;
                #pragma unroll
                for (int cl = 0; cl < CH; cl++) { float x = yv[cl * Wc + nl]; s += x * x; }
                yn2[v][nl] += s;
            }
            for (int col = t; col < 2 * bandn; col += 256) {
                int v = col / bandn, j = col - v * bandn;
                const float* zv = zsm + v * ZOFF1;
                float s = 0.f;
                #pragma unroll
                for (int cl = 0; cl < CH; cl++) { float x = zv[cl * BN + j]; s += x * x; }
                zn2[v][j] += s;
            }

            // column-owned pair dots: y column cached in registers
            if (dotthr && dcnt > 0) {
                const float* yv = ysm + dv * CH * Wc;
                const float* zv = zsm + dv * ZOFF1;
                float yreg[CH];
                #pragma unroll
                for (int cl = 0; cl < CH; cl++) yreg[cl] = yv[cl * Wc + dnl];
                #pragma unroll 1
                for (int k = 0; k < dcnt; k++) {
                    int j = s_jl[dg * MAXK + k];
                    float s = 0.f;
                    #pragma unroll
                    for (int cl = 0; cl < CH; cl++) s += yreg[cl] * zv[cl * BN + j];
                    s_dot[dg * MAXK + k] += s;
                }
            }
        }
        __syncthreads();

        // ---- per-pair cosine sims, double accumulation ----
        if (dotthr && dcnt > 0) {
            double ls = 0.0;
            for (int k = 0; k < dcnt; k++) {
                int j = s_jl[dg * MAXK + k];
                float den = fmaxf(__fsqrt_rn(yn2[dv][dnl] * zn2[dv][j]), 1e-8f);
                ls += (double)(s_dot[dg * MAXK + k] / den);
            }
            atomicAdd(&s_acc[dv], ls);
            atomicAdd(&s_pc[dv], (unsigned int)dcnt);
        }
    }
    __syncthreads();

    // ---- publish per-block partials + last-block finalize ----
    if (t == 0) {
        g_part[blk]        = s_acc[0];
        g_part[NBLK + blk] = s_acc[1];
        g_pcnt[blk]        = (int)s_pc[0];
        g_pcnt[NBLK + blk] = (int)s_pc[1];
        __threadfence();
        unsigned int old = atomicAdd(&g_done, 1u);
        s_last = (old == (unsigned int)(NBLK - 1)) ? 1 : 0;
    }
    __syncthreads();

    if (s_last) {
        __threadfence();   // acquire: all blocks' partials visible
        double s0 = 0.0, s1 = 0.0, c0 = 0.0, c1 = 0.0;
        for (int i = t; i < NBLK; i += 256) {
            s0 += g_part[i]; s1 += g_part[NBLK + i];
            c0 += (double)g_pcnt[i]; c1 += (double)g_pcnt[NBLK + i];
        }
        for (int off = 16; off; off >>= 1) {
            s0 += __shfl_down_sync(0xffffffffu, s0, off);
            s1 += __shfl_down_sync(0xffffffffu, s1, off);
            c0 += __shfl_down_sync(0xffffffffu, c0, off);
            c1 += __shfl_down_sync(0xffffffffu, c1, off);
        }
        int wid = t >> 5, lane = t & 31;
        if (lane == 0) { red_s0[wid] = s0; red_s1[wid] = s1; red_c0[wid] = c0; red_c1[wid] = c1; }
        __syncthreads();
        if (t == 0) {
            double S0 = 0, S1 = 0, C0 = 0, C1 = 0;
            #pragma unroll
            for (int w = 0; w < 8; w++) { S0 += red_s0[w]; S1 += red_s1[w]; C0 += red_c0[w]; C1 += red_c1[w]; }
            double l0 = (C0 > 0.0) ? S0 / C0 : 0.0;
            double l1 = (C1 > 0.0) ? S1 / C1 : 0.0;
            out[0] = (float)(-(l0 + l1));
            g_done = 0;   // reset for next (graph-replayed) call — deterministic
        }
    }
}

extern "C" void kernel_launch(void* const* d_in, const int* in_sizes, int n_in,
                              void* d_out, int out_size) {
    (void)in_sizes; (void)n_in; (void)out_size;
    const float* y1 = (const float*)d_in[0];
    const float* y2 = (const float*)d_in[1];
    const float* z1 = (const float*)d_in[2];
    const float* z2 = (const float*)d_in[3];
    const float* g1 = (const float*)d_in[4];
    const float* g2 = (const float*)d_in[5];

    dim3 grid(Hc, Bc);
    cl_main_kernel<<<grid, 256>>>(y1, y2, z1, z2, g1, g2, (float*)d_out);
}